// round 10
// baseline (speedup 1.0000x reference)
#include <cuda_runtime.h>
#include <cuda_bf16.h>
#include <stdint.h>
#include <math.h>

#define B_  2
#define L_  2048
#define D_  512
#define H_  8
#define KS_ 8

// ======================= scratch (device globals) ==========================
__device__ __nv_bfloat16 g_q_hi [(size_t)B_*L_*D_];
__device__ __nv_bfloat16 g_q_lo [(size_t)B_*L_*D_];
__device__ __nv_bfloat16 g_k_hi [(size_t)B_*L_*D_];
__device__ __nv_bfloat16 g_k_lo [(size_t)B_*L_*D_];
__device__ __nv_bfloat16 g_v_hi [(size_t)B_*L_*D_];
__device__ __nv_bfloat16 g_v_lo [(size_t)B_*L_*D_];
// concatenated weight operands: A4 = [WkT | Wo'], B4 = [WqT | WvT], C4 = [MT | P]
__device__ __nv_bfloat16 g_A4_hi[(size_t)2*H_*D_*D_];
__device__ __nv_bfloat16 g_A4_lo[(size_t)2*H_*D_*D_];
__device__ __nv_bfloat16 g_B4_hi[(size_t)2*H_*D_*D_];
__device__ __nv_bfloat16 g_B4_lo[(size_t)2*H_*D_*D_];
__device__ __nv_bfloat16 g_C4_hi[(size_t)2*H_*D_*D_];
__device__ __nv_bfloat16 g_C4_lo[(size_t)2*H_*D_*D_];
__device__ __nv_bfloat16 g_t_hi [(size_t)B_*H_*L_*D_];
__device__ __nv_bfloat16 g_t_lo [(size_t)B_*H_*L_*D_];
__device__ __nv_bfloat16 g_ZT_hi[(size_t)B_*D_*H_*L_];
__device__ __nv_bfloat16 g_ZT_lo[(size_t)B_*D_*H_*L_];
__device__ __nv_bfloat16 g_at_hi[(size_t)B_*L_*H_*L_];
__device__ __nv_bfloat16 g_at_lo[(size_t)B_*L_*H_*L_];
__device__ float         g_part [(size_t)B_*KS_*L_*D_];

// ======================= small helpers ======================================
__device__ __forceinline__ uint32_t smem_u32(const void* p) {
    uint32_t a;
    asm("{ .reg .u64 t; cvta.to.shared.u64 t, %1; cvt.u32.u64 %0, t; }"
        : "=r"(a) : "l"(p));
    return a;
}
// SW64 swizzle for 64-byte rows
__device__ __forceinline__ uint32_t swz64(uint32_t o) { return o ^ ((o >> 3) & 0x30); }

__device__ __forceinline__ void cp16(uint32_t s, const void* g) {
    asm volatile("cp.async.cg.shared.global [%0], [%1], 16;" :: "r"(s), "l"(g));
}
#define CP_COMMIT() asm volatile("cp.async.commit_group;" ::: "memory")

__device__ __forceinline__ void ldm4(uint32_t* r, uint32_t a) {
    asm volatile("ldmatrix.sync.aligned.m8n8.x4.shared.b16 {%0,%1,%2,%3}, [%4];"
                 : "=r"(r[0]), "=r"(r[1]), "=r"(r[2]), "=r"(r[3]) : "r"(a));
}
__device__ __forceinline__ void mma_bf16(float* c, const uint32_t* a, const uint32_t* b) {
    asm volatile("mma.sync.aligned.m16n8k16.row.col.f32.bf16.bf16.f32 "
                 "{%0,%1,%2,%3}, {%4,%5,%6,%7}, {%8,%9}, {%0,%1,%2,%3};"
                 : "+f"(c[0]), "+f"(c[1]), "+f"(c[2]), "+f"(c[3])
                 : "r"(a[0]), "r"(a[1]), "r"(a[2]), "r"(a[3]), "r"(b[0]), "r"(b[1]));
}
__device__ __forceinline__ void split2(float x, __nv_bfloat16& h, __nv_bfloat16& l) {
    h = __float2bfloat16(x);
    l = __float2bfloat16(x - __bfloat162float(h));
}
__device__ __forceinline__ void split_pack(float2 v, uint32_t& hi, uint32_t& lo) {
    __nv_bfloat16 h0, l0, h1, l1;
    split2(v.x, h0, l0);
    split2(v.y, h1, l1);
    hi = ((uint32_t)__bfloat16_as_ushort(h1) << 16) | __bfloat16_as_ushort(h0);
    lo = ((uint32_t)__bfloat16_as_ushort(l1) << 16) | __bfloat16_as_ushort(l0);
}

// ===== persistent bf16x3 HMMA GEMM, 256x128 CTA tile, 512 thr, KC=32 ========
// C[m,n] = alpha * sum_k A[m,k]*B[n,k]  (NT; A rows stride lda, B rows stride ldb)
// Tile t -> (z, ty, tx):  z = t/(gx*gy), ty = (t%(gx*gy))/gx, tx = t%gx
// A offset: ((z/adiv)%amod)*sA + (z%azmod)*sA2 + ty*256*lda
// B offset: ((z/bdiv)%bmod)*sB + (z%azmod)*sB2 + tx*128*ldb
// C offset: (z/czdiv)*sC1 + (z%czmod)*sC2 + ty*256*ldc + tx*128
#define KC       32
#define A_TILE   (256 * 64)           // 16 KB per limb (256 rows x 64B)
#define B_TILE   (128 * 64)           // 8 KB per limb
#define STAGE_B  (2 * A_TILE + 2 * B_TILE)  // 48 KB
#define NSTAGE   3
#define SMEM_T   (NSTAGE * STAGE_B)   // 144 KB
#define SM_BOFF  (2 * A_TILE)

struct TileP {
    const __nv_bfloat16 *ah, *al, *bh, *bl;
    long coff;
};

template <int MODE>   // 0: fp32 out, 1: bf16 hi/lo out
__global__ __launch_bounds__(512, 1)
void mma_gemm(const __nv_bfloat16* __restrict__ Ahi, const __nv_bfloat16* __restrict__ Alo,
              const __nv_bfloat16* __restrict__ Bhi, const __nv_bfloat16* __restrict__ Blo,
              float* __restrict__ C, __nv_bfloat16* __restrict__ Chi,
              __nv_bfloat16* __restrict__ Clo,
              int ntiles, int gx, int gy,
              int K, int lda, int ldb, int ldc,
              long sA, long sB, int adiv, int amod, int bdiv, int bmod,
              int azmod, long sA2, long sB2,
              int czdiv, long sC1, int czmod, long sC2, float alpha)
{
    extern __shared__ char smem[];
    const uint32_t sb = smem_u32(smem);
    const int tid  = threadIdx.x;
    const int lane = tid & 31, wid = tid >> 5;       // 16 warps
    const int moff = (wid & 3) * 64;                  // 4 M-quadrants of 64
    const int noff = (wid >> 2) * 32;                 // 4 N-quadrants of 32

    int t0 = blockIdx.x;
    if (t0 >= ntiles) return;

    auto tileinfo = [&](int t) -> TileP {
        const int gxy = gx * gy;
        const int z = t / gxy;
        const int r = t - z * gxy;
        const int ty = r / gx;
        const int tx = r - ty * gx;
        const long aoff = (long)((z / adiv) % amod) * sA + (long)(z % azmod) * sA2
                          + (long)ty * 256 * lda;
        const long boff = (long)((z / bdiv) % bmod) * sB + (long)(z % azmod) * sB2
                          + (long)tx * 128 * ldb;
        TileP p;
        p.ah = Ahi + aoff;  p.al = Alo + aoff;
        p.bh = Bhi + boff;  p.bl = Blo + boff;
        p.coff = (long)(z / czdiv) * sC1 + (long)(z % czmod) * sC2
                 + (long)ty * 256 * ldc + (long)tx * 128;
        return p;
    };

#define LOADT(T, cidx, stg) do {                                                 \
        const uint32_t st = sb + (stg) * STAGE_B;                                \
        const int k0 = (cidx) * KC;                                              \
        _Pragma("unroll")                                                        \
        for (int it = 0; it < 2; it++) {                                         \
            const int idx = tid + it * 512;          /* 0..1023: A slots */      \
            const int row = idx >> 2, ch = idx & 3;                              \
            const uint32_t so = swz64(row * 64 + ch * 16);                       \
            const long goA = (long)row * lda + k0 + ch * 8;                      \
            cp16(st + so,          (T).ah + goA);                                \
            cp16(st + A_TILE + so, (T).al + goA);                                \
        }                                                                        \
        {                                                                        \
            const int row = tid >> 2, ch = tid & 3;  /* 0..511: B slots */       \
            const uint32_t so = swz64(row * 64 + ch * 16);                       \
            const long goB = (long)row * ldb + k0 + ch * 8;                      \
            cp16(st + SM_BOFF + so,          (T).bh + goB);                      \
            cp16(st + SM_BOFF + B_TILE + so, (T).bl + goB);                      \
        }                                                                        \
    } while (0)

    const int NC = K / KC;               // >= 16 for all uses
    const int stride = gridDim.x;

    TileP cur = tileinfo(t0);
    LOADT(cur, 0, 0); CP_COMMIT();
    LOADT(cur, 1, 1); CP_COMMIT();
    int lstage = 2;
    int cstage = 0;

    const int arow = (lane & 7) + ((lane >> 3) & 1) * 8;
    const int ach  = (lane >> 4);
    const int brow = (lane & 7) + ((lane >> 4) & 1) * 8;
    const int bch  = ((lane >> 3) & 1);
    const int gq = lane >> 2, tg = lane & 3;

    for (int t = t0; t < ntiles; t += stride) {
        const int tn = t + stride;
        const bool has_next = tn < ntiles;
        TileP nxt = has_next ? tileinfo(tn) : cur;

        float acc[4][4][4];
#pragma unroll
        for (int a = 0; a < 4; a++)
#pragma unroll
            for (int b = 0; b < 4; b++)
#pragma unroll
                for (int c = 0; c < 4; c++) acc[a][b][c] = 0.f;

        for (int c = 0; c < NC; c++) {
            asm volatile("cp.async.wait_group 1;" ::: "memory");
            __syncthreads();
            const int cc = c + 2;
            if (cc < NC) {
                LOADT(cur, cc, lstage);
            } else if (has_next && cc - NC < 2) {
                LOADT(nxt, cc - NC, lstage);
            }
            CP_COMMIT();
            lstage = (lstage == 2) ? 0 : lstage + 1;

            const uint32_t st = sb + cstage * STAGE_B;
            cstage = (cstage == 2) ? 0 : cstage + 1;
#pragma unroll
            for (int kk = 0; kk < 2; kk++) {
                uint32_t ah[4][4], al[4][4], bh[4][2], bl[4][2];
#pragma unroll
                for (int mf = 0; mf < 4; mf++) {
                    uint32_t ad = st + swz64((moff + mf * 16 + arow) * 64 + (kk * 2 + ach) * 16);
                    ldm4(ah[mf], ad);
                    ldm4(al[mf], ad + A_TILE);
                }
#pragma unroll
                for (int p = 0; p < 2; p++) {
                    uint32_t bd = st + SM_BOFF +
                                  swz64((noff + p * 16 + brow) * 64 + (kk * 2 + bch) * 16);
                    uint32_t r[4];
                    ldm4(r, bd);
                    bh[2 * p][0] = r[0]; bh[2 * p][1] = r[1];
                    bh[2 * p + 1][0] = r[2]; bh[2 * p + 1][1] = r[3];
                    ldm4(r, bd + B_TILE);
                    bl[2 * p][0] = r[0]; bl[2 * p][1] = r[1];
                    bl[2 * p + 1][0] = r[2]; bl[2 * p + 1][1] = r[3];
                }
#pragma unroll
                for (int mf = 0; mf < 4; mf++)
#pragma unroll
                    for (int nf = 0; nf < 4; nf++) {
                        mma_bf16(acc[mf][nf], ah[mf], bh[nf]);
                        mma_bf16(acc[mf][nf], ah[mf], bl[nf]);
                        mma_bf16(acc[mf][nf], al[mf], bh[nf]);
                    }
            }
        }

        // ---- epilogue ----
#pragma unroll
        for (int mf = 0; mf < 4; mf++)
#pragma unroll
            for (int nf = 0; nf < 4; nf++) {
                const long row = moff + mf * 16 + gq;
                const long col = noff + nf * 8 + tg * 2;
                float v0 = alpha * acc[mf][nf][0];
                float v1 = alpha * acc[mf][nf][1];
                float v2 = alpha * acc[mf][nf][2];
                float v3 = alpha * acc[mf][nf][3];
                if (MODE == 0) {
                    float2 p0 = {v0, v1}, p1 = {v2, v3};
                    *reinterpret_cast<float2*>(C + cur.coff + row * ldc + col)       = p0;
                    *reinterpret_cast<float2*>(C + cur.coff + (row + 8) * ldc + col) = p1;
                } else {
                    uint32_t hp0, lp0, hp1, lp1;
                    split_pack({v0, v1}, hp0, lp0);
                    split_pack({v2, v3}, hp1, lp1);
                    *reinterpret_cast<uint32_t*>(Chi + cur.coff + row * ldc + col)       = hp0;
                    *reinterpret_cast<uint32_t*>(Clo + cur.coff + row * ldc + col)       = lp0;
                    *reinterpret_cast<uint32_t*>(Chi + cur.coff + (row + 8) * ldc + col) = hp1;
                    *reinterpret_cast<uint32_t*>(Clo + cur.coff + (row + 8) * ldc + col) = lp1;
                }
            }
        cur = nxt;
    }
#undef LOADT
}

// ======================= helper kernels =====================================
__global__ __launch_bounds__(256)
void split_qkv(const float4* __restrict__ q, const float4* __restrict__ k,
               const float4* __restrict__ v,
               uint2* __restrict__ qh, uint2* __restrict__ ql,
               uint2* __restrict__ kh, uint2* __restrict__ kl,
               uint2* __restrict__ vh, uint2* __restrict__ vl, int n4)
{
    int i = blockIdx.x * 256 + threadIdx.x;
    if (i >= n4) return;
    const int sel = blockIdx.y;
    const float4* s = (sel == 0) ? q : (sel == 1) ? k : v;
    uint2* hi = (sel == 0) ? qh : (sel == 1) ? kh : vh;
    uint2* lo = (sel == 0) ? ql : (sel == 1) ? kl : vl;
    float4 x = s[i];
    __nv_bfloat16 h[4], l[4];
    split2(x.x, h[0], l[0]);
    split2(x.y, h[1], l[1]);
    split2(x.z, h[2], l[2]);
    split2(x.w, h[3], l[3]);
    hi[i] = *reinterpret_cast<uint2*>(h);
    lo[i] = *reinterpret_cast<uint2*>(l);
}

__global__ __launch_bounds__(256)
void transpose_split_w3(const float* __restrict__ Wq, const float* __restrict__ Wk,
                        const float* __restrict__ Wv,
                        __nv_bfloat16* __restrict__ qhi, __nv_bfloat16* __restrict__ qlo,
                        __nv_bfloat16* __restrict__ khi, __nv_bfloat16* __restrict__ klo,
                        __nv_bfloat16* __restrict__ vhi, __nv_bfloat16* __restrict__ vlo)
{
    __shared__ float t[32][33];
    const int zz = blockIdx.z;
    const int w = zz >> 3, z = zz & 7;
    const float* src = (w == 0) ? Wq : (w == 1) ? Wk : Wv;
    __nv_bfloat16* hi = (w == 0) ? qhi : (w == 1) ? khi : vhi;
    __nv_bfloat16* lo = (w == 0) ? qlo : (w == 1) ? klo : vlo;

    const int e0 = blockIdx.y * 32, d0 = blockIdx.x * 32;
    const int tx = threadIdx.x & 31, ty = threadIdx.x >> 5;
    const float* s = src + (long)z * D_ * D_;
#pragma unroll
    for (int r = 0; r < 32; r += 8)
        t[ty + r][tx] = s[(long)(e0 + ty + r) * D_ + d0 + tx];
    __syncthreads();
    const long base = (long)z * D_ * D_;
#pragma unroll
    for (int r = 0; r < 32; r += 8) {
        float x = t[tx][ty + r];
        __nv_bfloat16 h, l;
        split2(x, h, l);
        long o = base + (long)(d0 + ty + r) * D_ + e0 + tx;
        hi[o] = h; lo[o] = l;
    }
}

__global__ __launch_bounds__(256)
void wo_permute_split(const float* __restrict__ Wo,
                      __nv_bfloat16* __restrict__ hi, __nv_bfloat16* __restrict__ lo)
{
    long idx = (long)blockIdx.x * 256 + threadIdx.x;
    int f = (int)(idx & 511);
    int e = (int)((idx >> 9) & 511);
    int h = (int)(idx >> 18);
    float x = Wo[(long)e * (H_ * D_) + (f >> 6) * 512 + h * 64 + (f & 63)];
    __nv_bfloat16 hb, lb;
    split2(x, hb, lb);
    hi[idx] = hb; lo[idx] = lb;
}

__global__ __launch_bounds__(256)
void softmax_split(float* __restrict__ data,
                   uint32_t* __restrict__ hi, uint32_t* __restrict__ lo)
{
    const int r = blockIdx.x;
    const int b = r >> 14;
    const int h = (r >> 11) & (H_ - 1);
    const int l = r & (L_ - 1);
    float2* p = reinterpret_cast<float2*>(data + (long)r * L_);
    const long ob2 = ((((long)b * L_ + l) * H_ + h) * L_) >> 1;
    const int tid = threadIdx.x;

    float2 vals[4];
    float vmax = -1e30f;
#pragma unroll
    for (int i = 0; i < 4; i++) {
        vals[i] = p[tid + i * 256];
        vmax = fmaxf(vmax, fmaxf(vals[i].x, vals[i].y));
    }
#pragma unroll
    for (int o = 16; o > 0; o >>= 1) vmax = fmaxf(vmax, __shfl_xor_sync(0xFFFFFFFFu, vmax, o));

    __shared__ float smax[8], ssum[8];
    if ((tid & 31) == 0) smax[tid >> 5] = vmax;
    __syncthreads();
    float m = smax[0];
#pragma unroll
    for (int i = 1; i < 8; i++) m = fmaxf(m, smax[i]);

    float sum = 0.f;
#pragma unroll
    for (int i = 0; i < 4; i++) {
        vals[i].x = __expf(vals[i].x - m);
        vals[i].y = __expf(vals[i].y - m);
        sum += vals[i].x + vals[i].y;
    }
#pragma unroll
    for (int o = 16; o > 0; o >>= 1) sum += __shfl_xor_sync(0xFFFFFFFFu, sum, o);
    if ((tid & 31) == 0) ssum[tid >> 5] = sum;
    __syncthreads();
    float tot = 0.f;
#pragma unroll
    for (int i = 0; i < 8; i++) tot += ssum[i];
    const float inv = 1.f / tot;
#pragma unroll
    for (int i = 0; i < 4; i++) {
        float2 y = {vals[i].x * inv, vals[i].y * inv};
        p[tid + i * 256] = y;
        uint32_t hp, lp;
        split_pack(y, hp, lp);
        hi[ob2 + tid + i * 256] = hp;
        lo[ob2 + tid + i * 256] = lp;
    }
}

__global__ __launch_bounds__(256)
void reduce_part(const float4* __restrict__ part, float4* __restrict__ out)
{
    const int LD4 = L_ * D_ / 4;
    long idx = (long)blockIdx.x * 256 + threadIdx.x;
    int b = (int)(idx / LD4);
    long j = idx - (long)b * LD4;
    const float4* p = part + (long)b * KS_ * LD4 + j;
    float4 s = p[0];
#pragma unroll
    for (int ks = 1; ks < KS_; ks++) {
        float4 t = p[(long)ks * LD4];
        s.x += t.x; s.y += t.y; s.z += t.z; s.w += t.w;
    }
    out[idx] = s;
}

// ======================= launch =============================================
extern "C" void kernel_launch(void* const* d_in, const int* in_sizes, int n_in,
                              void* d_out, int out_size)
{
    const float* q  = (const float*)d_in[0];
    const float* k  = (const float*)d_in[1];
    const float* v  = (const float*)d_in[2];
    const float* Wq = (const float*)d_in[3];
    const float* Wk = (const float*)d_in[4];
    const float* Wv = (const float*)d_in[5];
    const float* Wo = (const float*)d_in[6];

    float* out  = (float*)d_out;
    float* attn = out + (long)B_ * L_ * D_;

    static int nsm = 0;
    if (!nsm) {
        cudaDeviceGetAttribute(&nsm, cudaDevAttrMultiProcessorCount, 0);
        cudaFuncSetAttribute(mma_gemm<0>, cudaFuncAttributeMaxDynamicSharedMemorySize, SMEM_T);
        cudaFuncSetAttribute(mma_gemm<1>, cudaFuncAttributeMaxDynamicSharedMemorySize, SMEM_T);
        if (nsm <= 0) nsm = 148;
    }

#define SYM(p, s) cudaGetSymbolAddress((void**)&p, s)
    __nv_bfloat16 *q_hi, *q_lo, *k_hi, *k_lo, *v_hi, *v_lo;
    __nv_bfloat16 *A4_hi, *A4_lo, *B4_hi, *B4_lo, *C4_hi, *C4_lo;
    __nv_bfloat16 *t_hi, *t_lo, *ZT_hi, *ZT_lo, *at_hi, *at_lo;
    float *part;
    SYM(q_hi, g_q_hi);  SYM(q_lo, g_q_lo);
    SYM(k_hi, g_k_hi);  SYM(k_lo, g_k_lo);
    SYM(v_hi, g_v_hi);  SYM(v_lo, g_v_lo);
    SYM(A4_hi, g_A4_hi); SYM(A4_lo, g_A4_lo);
    SYM(B4_hi, g_B4_hi); SYM(B4_lo, g_B4_lo);
    SYM(C4_hi, g_C4_hi); SYM(C4_lo, g_C4_lo);
    SYM(t_hi, g_t_hi);   SYM(t_lo, g_t_lo);
    SYM(ZT_hi, g_ZT_hi); SYM(ZT_lo, g_ZT_lo);
    SYM(at_hi, g_at_hi); SYM(at_lo, g_at_lo);
    SYM(part, g_part);
#undef SYM

    const long sLD = (long)L_ * D_;
    const long sLL = (long)L_ * L_;
    const long sDD = (long)D_ * D_;
    const long HDD = (long)H_ * D_ * D_;
    const float inv_sqrt_d = 1.0f / sqrtf((float)D_);

    dim3 blk(256);
    dim3 blkg(512);
    const int n4_in = (B_ * L_ * D_) / 4;

    // launch 0: merged q/k/v splits
    dim3 gsp((n4_in + 255) / 256, 3);
    split_qkv<<<gsp, blk>>>((const float4*)q, (const float4*)k, (const float4*)v,
        (uint2*)q_hi, (uint2*)q_lo, (uint2*)k_hi, (uint2*)k_lo,
        (uint2*)v_hi, (uint2*)v_lo, n4_in);

    // launch 1: merged Wq/Wk/Wv transpose-splits:
    //   WqT -> B4[0:8], WkT -> A4[0:8], WvT -> B4[8:16]
    dim3 gtw(D_ / 32, D_ / 32, 3 * H_);
    transpose_split_w3<<<gtw, blk>>>(Wq, Wk, Wv,
        B4_hi, B4_lo, A4_hi, A4_lo, B4_hi + HDD, B4_lo + HDD);

    // launch 2: Wo permute-split -> A4[8:16]
    wo_permute_split<<<(H_ * D_ * D_) / 256, blk>>>(Wo, A4_hi + HDD, A4_lo + HDD);

    // launch 3: C4[z] = A4[z] @ B4[z]^T  (z=16 heads: MT=C4[0:8], P=C4[8:16])
    //   tiles: gy=2, gx=4, z=16 -> 128
    mma_gemm<1><<<nsm, blkg, SMEM_T>>>(A4_hi, A4_lo, B4_hi, B4_lo,
        nullptr, C4_hi, C4_lo,
        128, 4, 2, D_, D_, D_, D_, sDD, sDD, 1, 2 * H_, 1, 2 * H_, 1, 0, 0,
        1, sDD, 1, 0, 1.0f);

    // launch 4: t[b,h] = q[b] @ MT[h]^T   (gy=8, gx=4, z=16 -> 512 tiles)
    mma_gemm<1><<<nsm, blkg, SMEM_T>>>(q_hi, q_lo, C4_hi, C4_lo,
        nullptr, t_hi, t_lo,
        512, 4, 8, D_, D_, D_, D_, sLD, sDD, H_, B_, 1, H_, 1, 0, 0,
        1, sLD, 1, 0, 1.0f);

    // launch 5 (ncu capture): scores = t @ k^T / sqrt(D)  (gy=8, gx=16, z=16 -> 2048)
    mma_gemm<0><<<nsm, blkg, SMEM_T>>>(t_hi, t_lo, k_hi, k_lo,
        attn, nullptr, nullptr,
        2048, 16, 8, D_, D_, D_, L_, sLD, sLD, 1, B_ * H_, H_, B_, 1, 0, 0,
        1, sLL, 1, 0, inv_sqrt_d);

    // launch 6: ZT[b, e, h*L+m] = P[h] @ v[b]^T  (gy=2, gx=16, z=16 -> 512)
    mma_gemm<1><<<nsm, blkg, SMEM_T>>>(C4_hi + HDD, C4_lo + HDD, v_hi, v_lo,
        nullptr, ZT_hi, ZT_lo,
        512, 16, 2, D_, D_, D_, H_ * L_, sDD, sLD, 1, H_, H_, B_, 1, 0, 0,
        H_, (long)D_ * H_ * L_, H_, (long)L_, 1.0f);

    // launch 7: softmax in place + bf16 hi/lo in permuted [b,l,h,m] layout
    softmax_split<<<B_ * H_ * L_, blk>>>(attn, (uint32_t*)at_hi, (uint32_t*)at_lo);

    // launch 8: out partials, split-K=8 over H*L (gy=8, gx=4, z=16 -> 512 tiles)
    mma_gemm<0><<<nsm, blkg, SMEM_T>>>(at_hi, at_lo, ZT_hi, ZT_lo,
        part, nullptr, nullptr,
        512, 4, 8, (H_ * L_) / KS_, H_ * L_, H_ * L_, D_,
        (long)L_ * H_ * L_, (long)D_ * H_ * L_, KS_, B_, KS_, B_,
        KS_, (H_ * L_) / KS_, (H_ * L_) / KS_,
        1, sLD, 1, 0, 1.0f);

    // launch 9: reduce partials -> out
    reduce_part<<<(B_ * L_ * D_ / 4) / 256, blk>>>((const float4*)part, (float4*)out);
}

// round 11
// speedup vs baseline: 1.2210x; 1.2210x over previous
#include <cuda_runtime.h>
#include <cuda_bf16.h>
#include <stdint.h>
#include <math.h>

#define B_  2
#define L_  2048
#define D_  512
#define H_  8
#define KS_ 8

// ======================= scratch (device globals) ==========================
__device__ __nv_bfloat16 g_q_hi [(size_t)B_*L_*D_];
__device__ __nv_bfloat16 g_q_lo [(size_t)B_*L_*D_];
__device__ __nv_bfloat16 g_k_hi [(size_t)B_*L_*D_];
__device__ __nv_bfloat16 g_k_lo [(size_t)B_*L_*D_];
__device__ __nv_bfloat16 g_v_hi [(size_t)B_*L_*D_];
__device__ __nv_bfloat16 g_v_lo [(size_t)B_*L_*D_];
// concatenated: A4 = [WkT | Wo'], B4 = [WqT | WvT], C4 = [MT | P]
__device__ __nv_bfloat16 g_A4_hi[(size_t)2*H_*D_*D_];
__device__ __nv_bfloat16 g_A4_lo[(size_t)2*H_*D_*D_];
__device__ __nv_bfloat16 g_B4_hi[(size_t)2*H_*D_*D_];
__device__ __nv_bfloat16 g_B4_lo[(size_t)2*H_*D_*D_];
__device__ __nv_bfloat16 g_C4_hi[(size_t)2*H_*D_*D_];
__device__ __nv_bfloat16 g_C4_lo[(size_t)2*H_*D_*D_];
__device__ __nv_bfloat16 g_t_hi [(size_t)B_*H_*L_*D_];
__device__ __nv_bfloat16 g_t_lo [(size_t)B_*H_*L_*D_];
__device__ __nv_bfloat16 g_ZT_hi[(size_t)B_*D_*H_*L_];
__device__ __nv_bfloat16 g_ZT_lo[(size_t)B_*D_*H_*L_];
__device__ __nv_bfloat16 g_at_hi[(size_t)B_*L_*H_*L_];
__device__ __nv_bfloat16 g_at_lo[(size_t)B_*L_*H_*L_];
__device__ float         g_part [(size_t)B_*KS_*L_*D_];

// ======================= small helpers ======================================
__device__ __forceinline__ uint32_t smem_u32(const void* p) {
    uint32_t a;
    asm("{ .reg .u64 t; cvta.to.shared.u64 t, %1; cvt.u32.u64 %0, t; }"
        : "=r"(a) : "l"(p));
    return a;
}
__device__ __forceinline__ uint32_t swz128(uint32_t o) { return o ^ ((o >> 3) & 0x70); }

__device__ __forceinline__ void cp16(uint32_t s, const void* g) {
    asm volatile("cp.async.cg.shared.global [%0], [%1], 16;" :: "r"(s), "l"(g));
}
#define CP_COMMIT() asm volatile("cp.async.commit_group;" ::: "memory")

__device__ __forceinline__ void ldm4(uint32_t* r, uint32_t a) {
    asm volatile("ldmatrix.sync.aligned.m8n8.x4.shared.b16 {%0,%1,%2,%3}, [%4];"
                 : "=r"(r[0]), "=r"(r[1]), "=r"(r[2]), "=r"(r[3]) : "r"(a));
}
__device__ __forceinline__ void mma_bf16(float* c, const uint32_t* a, const uint32_t* b) {
    asm volatile("mma.sync.aligned.m16n8k16.row.col.f32.bf16.bf16.f32 "
                 "{%0,%1,%2,%3}, {%4,%5,%6,%7}, {%8,%9}, {%0,%1,%2,%3};"
                 : "+f"(c[0]), "+f"(c[1]), "+f"(c[2]), "+f"(c[3])
                 : "r"(a[0]), "r"(a[1]), "r"(a[2]), "r"(a[3]), "r"(b[0]), "r"(b[1]));
}
__device__ __forceinline__ void split2(float x, __nv_bfloat16& h, __nv_bfloat16& l) {
    h = __float2bfloat16(x);
    l = __float2bfloat16(x - __bfloat162float(h));
}
__device__ __forceinline__ void split_pack(float2 v, uint32_t& hi, uint32_t& lo) {
    __nv_bfloat16 h0, l0, h1, l1;
    split2(v.x, h0, l0);
    split2(v.y, h1, l1);
    hi = ((uint32_t)__bfloat16_as_ushort(h1) << 16) | __bfloat16_as_ushort(h0);
    lo = ((uint32_t)__bfloat16_as_ushort(l1) << 16) | __bfloat16_as_ushort(l0);
}

// =============== persistent bf16x3 HMMA GEMM (KC=64, 3-stage) ===============
// (exact round-8 engine: 128x128 tile, 256 threads, single sync per chunk)
#define KC       64
#define TILE_B   (128 * 128)
#define STAGE_B  (4 * TILE_B)
#define NSTAGE   3
#define SMEM_T   (NSTAGE * STAGE_B)   // 192 KB

struct TileP {
    const __nv_bfloat16 *ah, *al, *bh, *bl;
    long coff;
};

template <int MODE>   // 0: fp32 out, 1: bf16 hi/lo out
__global__ __launch_bounds__(256, 1)
void mma_gemm(const __nv_bfloat16* __restrict__ Ahi, const __nv_bfloat16* __restrict__ Alo,
              const __nv_bfloat16* __restrict__ Bhi, const __nv_bfloat16* __restrict__ Blo,
              float* __restrict__ C, __nv_bfloat16* __restrict__ Chi,
              __nv_bfloat16* __restrict__ Clo,
              int ntiles, int gx, int gy,
              int K, int lda, int ldb, int ldc,
              long sA, long sB, int adiv, int amod, int bdiv, int bmod,
              int azmod, long sA2, long sB2,
              int czdiv, long sC1, int czmod, long sC2, float alpha)
{
    extern __shared__ char smem[];
    const uint32_t sb = smem_u32(smem);
    const int tid  = threadIdx.x;
    const int lane = tid & 31, wid = tid >> 5;
    const int moff = (wid & 1) * 64;
    const int noff = (wid >> 1) * 32;

    int t0 = blockIdx.x;
    if (t0 >= ntiles) return;

    auto tileinfo = [&](int t) -> TileP {
        const int gxy = gx * gy;
        const int z = t / gxy;
        const int r = t - z * gxy;
        const int ty = r / gx;
        const int tx = r - ty * gx;
        const long aoff = (long)((z / adiv) % amod) * sA + (long)(z % azmod) * sA2
                          + (long)ty * 128 * lda;
        const long boff = (long)((z / bdiv) % bmod) * sB + (long)(z % azmod) * sB2
                          + (long)tx * 128 * ldb;
        TileP p;
        p.ah = Ahi + aoff;  p.al = Alo + aoff;
        p.bh = Bhi + boff;  p.bl = Blo + boff;
        p.coff = (long)(z / czdiv) * sC1 + (long)(z % czmod) * sC2
                 + (long)ty * 128 * ldc + (long)tx * 128;
        return p;
    };

#define LOADT(T, cidx, stg) do {                                                 \
        const uint32_t st = sb + (stg) * STAGE_B;                                \
        const int k0 = (cidx) * KC;                                              \
        _Pragma("unroll")                                                        \
        for (int it = 0; it < 4; it++) {                                         \
            const int idx = tid + it * 256;                                      \
            const int row = idx >> 3, ch = idx & 7;                              \
            const uint32_t so = swz128(row * 128 + ch * 16);                     \
            const long goA = (long)row * lda + k0 + ch * 8;                      \
            const long goB = (long)row * ldb + k0 + ch * 8;                      \
            cp16(st + so,              (T).ah + goA);                            \
            cp16(st + TILE_B + so,     (T).al + goA);                            \
            cp16(st + 2 * TILE_B + so, (T).bh + goB);                            \
            cp16(st + 3 * TILE_B + so, (T).bl + goB);                            \
        }                                                                        \
    } while (0)

    const int NC = K / KC;
    const int stride = gridDim.x;

    TileP cur = tileinfo(t0);
    LOADT(cur, 0, 0); CP_COMMIT();
    LOADT(cur, 1, 1); CP_COMMIT();
    int lstage = 2;
    int cstage = 0;

    const int arow = (lane & 7) + ((lane >> 3) & 1) * 8;
    const int ach  = (lane >> 4);
    const int brow = (lane & 7) + ((lane >> 4) & 1) * 8;
    const int bch  = ((lane >> 3) & 1);
    const int gq = lane >> 2, tg = lane & 3;

    for (int t = t0; t < ntiles; t += stride) {
        const int tn = t + stride;
        const bool has_next = tn < ntiles;
        TileP nxt = has_next ? tileinfo(tn) : cur;

        float acc[4][4][4];
#pragma unroll
        for (int a = 0; a < 4; a++)
#pragma unroll
            for (int b = 0; b < 4; b++)
#pragma unroll
                for (int c = 0; c < 4; c++) acc[a][b][c] = 0.f;

        for (int c = 0; c < NC; c++) {
            asm volatile("cp.async.wait_group 1;" ::: "memory");
            __syncthreads();
            const int cc = c + 2;
            if (cc < NC) {
                LOADT(cur, cc, lstage);
            } else if (has_next && cc - NC < 2) {
                LOADT(nxt, cc - NC, lstage);
            }
            CP_COMMIT();
            lstage = (lstage == 2) ? 0 : lstage + 1;

            const uint32_t st = sb + cstage * STAGE_B;
            cstage = (cstage == 2) ? 0 : cstage + 1;
#pragma unroll
            for (int kk = 0; kk < 4; kk++) {
                uint32_t ah[4][4], al[4][4], bh[4][2], bl[4][2];
#pragma unroll
                for (int mf = 0; mf < 4; mf++) {
                    uint32_t ad = st + swz128((moff + mf * 16 + arow) * 128 + (kk * 2 + ach) * 16);
                    ldm4(ah[mf], ad);
                    ldm4(al[mf], ad + TILE_B);
                }
#pragma unroll
                for (int p = 0; p < 2; p++) {
                    uint32_t bd = st + 2 * TILE_B +
                                  swz128((noff + p * 16 + brow) * 128 + (kk * 2 + bch) * 16);
                    uint32_t r[4];
                    ldm4(r, bd);
                    bh[2 * p][0] = r[0]; bh[2 * p][1] = r[1];
                    bh[2 * p + 1][0] = r[2]; bh[2 * p + 1][1] = r[3];
                    ldm4(r, bd + TILE_B);
                    bl[2 * p][0] = r[0]; bl[2 * p][1] = r[1];
                    bl[2 * p + 1][0] = r[2]; bl[2 * p + 1][1] = r[3];
                }
#pragma unroll
                for (int mf = 0; mf < 4; mf++)
#pragma unroll
                    for (int nf = 0; nf < 4; nf++) {
                        mma_bf16(acc[mf][nf], ah[mf], bh[nf]);
                        mma_bf16(acc[mf][nf], ah[mf], bl[nf]);
                        mma_bf16(acc[mf][nf], al[mf], bh[nf]);
                    }
            }
        }

        // ---- epilogue ----
#pragma unroll
        for (int mf = 0; mf < 4; mf++)
#pragma unroll
            for (int nf = 0; nf < 4; nf++) {
                const long row = moff + mf * 16 + gq;
                const long col = noff + nf * 8 + tg * 2;
                float v0 = alpha * acc[mf][nf][0];
                float v1 = alpha * acc[mf][nf][1];
                float v2 = alpha * acc[mf][nf][2];
                float v3 = alpha * acc[mf][nf][3];
                if (MODE == 0) {
                    float2 p0 = {v0, v1}, p1 = {v2, v3};
                    *reinterpret_cast<float2*>(C + cur.coff + row * ldc + col)       = p0;
                    *reinterpret_cast<float2*>(C + cur.coff + (row + 8) * ldc + col) = p1;
                } else {
                    uint32_t hp0, lp0, hp1, lp1;
                    split_pack({v0, v1}, hp0, lp0);
                    split_pack({v2, v3}, hp1, lp1);
                    *reinterpret_cast<uint32_t*>(Chi + cur.coff + row * ldc + col)       = hp0;
                    *reinterpret_cast<uint32_t*>(Clo + cur.coff + row * ldc + col)       = lp0;
                    *reinterpret_cast<uint32_t*>(Chi + cur.coff + (row + 8) * ldc + col) = hp1;
                    *reinterpret_cast<uint32_t*>(Clo + cur.coff + (row + 8) * ldc + col) = lp1;
                }
            }
        cur = nxt;
    }
#undef LOADT
}

// ======================= helper kernels =====================================
__global__ __launch_bounds__(256)
void split_qkv(const float4* __restrict__ q, const float4* __restrict__ k,
               const float4* __restrict__ v,
               uint2* __restrict__ qh, uint2* __restrict__ ql,
               uint2* __restrict__ kh, uint2* __restrict__ kl,
               uint2* __restrict__ vh, uint2* __restrict__ vl, int n4)
{
    int i = blockIdx.x * 256 + threadIdx.x;
    if (i >= n4) return;
    const int sel = blockIdx.y;
    const float4* s = (sel == 0) ? q : (sel == 1) ? k : v;
    uint2* hi = (sel == 0) ? qh : (sel == 1) ? kh : vh;
    uint2* lo = (sel == 0) ? ql : (sel == 1) ? kl : vl;
    float4 x = s[i];
    __nv_bfloat16 h[4], l[4];
    split2(x.x, h[0], l[0]);
    split2(x.y, h[1], l[1]);
    split2(x.z, h[2], l[2]);
    split2(x.w, h[3], l[3]);
    hi[i] = *reinterpret_cast<uint2*>(h);
    lo[i] = *reinterpret_cast<uint2*>(l);
}

// merged weight prep: zz = w*8 + h; w<3 transpose-split, w==3 Wo permute-split
//  w0: Wq^T -> B4[0:8] | w1: Wk^T -> A4[0:8] | w2: Wv^T -> B4[8:16] | w3: Wo' -> A4[8:16]
__global__ __launch_bounds__(256)
void prep_weights(const float* __restrict__ Wq, const float* __restrict__ Wk,
                  const float* __restrict__ Wv, const float* __restrict__ Wo,
                  __nv_bfloat16* __restrict__ A4hi, __nv_bfloat16* __restrict__ A4lo,
                  __nv_bfloat16* __restrict__ B4hi, __nv_bfloat16* __restrict__ B4lo)
{
    __shared__ float t[32][33];
    const int zz = blockIdx.z;
    const int w = zz >> 3, z = zz & 7;
    const long HDD = (long)H_ * D_ * D_;
    const int tx = threadIdx.x & 31, ty = threadIdx.x >> 5;

    if (w == 3) {
        // Wo'[h][e,f] = Wo[e, (f/64)*512 + h*64 + (f%64)] -> A4[8+h]
        const int e0 = blockIdx.y * 32, f0 = blockIdx.x * 32;
        const long base = HDD + (long)z * D_ * D_;
#pragma unroll
        for (int r = 0; r < 32; r += 8) {
            const int e = e0 + ty + r, f = f0 + tx;
            float x = Wo[(long)e * (H_ * D_) + (f >> 6) * 512 + z * 64 + (f & 63)];
            __nv_bfloat16 h, l;
            split2(x, h, l);
            long o = base + (long)e * D_ + f;
            A4hi[o] = h; A4lo[o] = l;
        }
        return;
    }

    const float* src = (w == 0) ? Wq : (w == 1) ? Wk : Wv;
    __nv_bfloat16* hi = (w == 0) ? B4hi : (w == 1) ? A4hi : (B4hi + HDD);
    __nv_bfloat16* lo = (w == 0) ? B4lo : (w == 1) ? A4lo : (B4lo + HDD);

    const int e0 = blockIdx.y * 32, d0 = blockIdx.x * 32;
    const float* s = src + (long)z * D_ * D_;
#pragma unroll
    for (int r = 0; r < 32; r += 8)
        t[ty + r][tx] = s[(long)(e0 + ty + r) * D_ + d0 + tx];
    __syncthreads();
    const long base = (long)z * D_ * D_;
#pragma unroll
    for (int r = 0; r < 32; r += 8) {
        float x = t[tx][ty + r];
        __nv_bfloat16 h, l;
        split2(x, h, l);
        long o = base + (long)(d0 + ty + r) * D_ + e0 + tx;
        hi[o] = h; lo[o] = l;
    }
}

// softmax over rows of 2048 in place (fp32, [b,h,l,m]) + bf16 hi/lo in [b,l,h,m]
// float4-vectorized: each thread handles 2 float4 groups
__global__ __launch_bounds__(256)
void softmax_split(float* __restrict__ data,
                   uint2* __restrict__ hi, uint2* __restrict__ lo)
{
    const int r = blockIdx.x;
    const int b = r >> 14;
    const int h = (r >> 11) & (H_ - 1);
    const int l = r & (L_ - 1);
    float4* p = reinterpret_cast<float4*>(data + (long)r * L_);
    const long ob4 = ((((long)b * L_ + l) * H_ + h) * L_) >> 2;   // in uint2 (4 bf16) units
    const int tid = threadIdx.x;

    float4 vals[2];
    float vmax = -1e30f;
#pragma unroll
    for (int i = 0; i < 2; i++) {
        vals[i] = p[tid + i * 256];
        vmax = fmaxf(vmax, fmaxf(fmaxf(vals[i].x, vals[i].y), fmaxf(vals[i].z, vals[i].w)));
    }
#pragma unroll
    for (int o = 16; o > 0; o >>= 1) vmax = fmaxf(vmax, __shfl_xor_sync(0xFFFFFFFFu, vmax, o));

    __shared__ float smax[8], ssum[8];
    if ((tid & 31) == 0) smax[tid >> 5] = vmax;
    __syncthreads();
    float m = smax[0];
#pragma unroll
    for (int i = 1; i < 8; i++) m = fmaxf(m, smax[i]);

    float sum = 0.f;
#pragma unroll
    for (int i = 0; i < 2; i++) {
        vals[i].x = __expf(vals[i].x - m);
        vals[i].y = __expf(vals[i].y - m);
        vals[i].z = __expf(vals[i].z - m);
        vals[i].w = __expf(vals[i].w - m);
        sum += (vals[i].x + vals[i].y) + (vals[i].z + vals[i].w);
    }
#pragma unroll
    for (int o = 16; o > 0; o >>= 1) sum += __shfl_xor_sync(0xFFFFFFFFu, sum, o);
    if ((tid & 31) == 0) ssum[tid >> 5] = sum;
    __syncthreads();
    float tot = 0.f;
#pragma unroll
    for (int i = 0; i < 8; i++) tot += ssum[i];
    const float inv = 1.f / tot;
#pragma unroll
    for (int i = 0; i < 2; i++) {
        float4 y;
        y.x = vals[i].x * inv; y.y = vals[i].y * inv;
        y.z = vals[i].z * inv; y.w = vals[i].w * inv;
        p[tid + i * 256] = y;
        uint2 hp, lp;
        split_pack({y.x, y.y}, hp.x, lp.x);
        split_pack({y.z, y.w}, hp.y, lp.y);
        hi[ob4 + tid + i * 256] = hp;
        lo[ob4 + tid + i * 256] = lp;
    }
}

// reduce partials: out[b][j] = sum_ks part[b*KS+ks][j]
__global__ __launch_bounds__(256)
void reduce_part(const float4* __restrict__ part, float4* __restrict__ out)
{
    const int LD4 = L_ * D_ / 4;
    long idx = (long)blockIdx.x * 256 + threadIdx.x;
    int b = (int)(idx / LD4);
    long j = idx - (long)b * LD4;
    const float4* p = part + (long)b * KS_ * LD4 + j;
    float4 s = p[0];
#pragma unroll
    for (int ks = 1; ks < KS_; ks++) {
        float4 t = p[(long)ks * LD4];
        s.x += t.x; s.y += t.y; s.z += t.z; s.w += t.w;
    }
    out[idx] = s;
}

// ======================= launch =============================================
extern "C" void kernel_launch(void* const* d_in, const int* in_sizes, int n_in,
                              void* d_out, int out_size)
{
    const float* q  = (const float*)d_in[0];
    const float* k  = (const float*)d_in[1];
    const float* v  = (const float*)d_in[2];
    const float* Wq = (const float*)d_in[3];
    const float* Wk = (const float*)d_in[4];
    const float* Wv = (const float*)d_in[5];
    const float* Wo = (const float*)d_in[6];

    float* out  = (float*)d_out;
    float* attn = out + (long)B_ * L_ * D_;

    static int nsm = 0;
    if (!nsm) {
        cudaDeviceGetAttribute(&nsm, cudaDevAttrMultiProcessorCount, 0);
        cudaFuncSetAttribute(mma_gemm<0>, cudaFuncAttributeMaxDynamicSharedMemorySize, SMEM_T);
        cudaFuncSetAttribute(mma_gemm<1>, cudaFuncAttributeMaxDynamicSharedMemorySize, SMEM_T);
        if (nsm <= 0) nsm = 148;
    }

#define SYM(p, s) cudaGetSymbolAddress((void**)&p, s)
    __nv_bfloat16 *q_hi, *q_lo, *k_hi, *k_lo, *v_hi, *v_lo;
    __nv_bfloat16 *A4_hi, *A4_lo, *B4_hi, *B4_lo, *C4_hi, *C4_lo;
    __nv_bfloat16 *t_hi, *t_lo, *ZT_hi, *ZT_lo, *at_hi, *at_lo;
    float *part;
    SYM(q_hi, g_q_hi);  SYM(q_lo, g_q_lo);
    SYM(k_hi, g_k_hi);  SYM(k_lo, g_k_lo);
    SYM(v_hi, g_v_hi);  SYM(v_lo, g_v_lo);
    SYM(A4_hi, g_A4_hi); SYM(A4_lo, g_A4_lo);
    SYM(B4_hi, g_B4_hi); SYM(B4_lo, g_B4_lo);
    SYM(C4_hi, g_C4_hi); SYM(C4_lo, g_C4_lo);
    SYM(t_hi, g_t_hi);   SYM(t_lo, g_t_lo);
    SYM(ZT_hi, g_ZT_hi); SYM(ZT_lo, g_ZT_lo);
    SYM(at_hi, g_at_hi); SYM(at_lo, g_at_lo);
    SYM(part, g_part);
#undef SYM

    const long sLD = (long)L_ * D_;
    const long sLL = (long)L_ * L_;
    const long sDD = (long)D_ * D_;
    const long HDD = (long)H_ * D_ * D_;
    const float inv_sqrt_d = 1.0f / sqrtf((float)D_);

    dim3 blk(256);
    const int n4_in = (B_ * L_ * D_) / 4;

    // launch 0: merged q/k/v splits
    dim3 gsp((n4_in + 255) / 256, 3);
    split_qkv<<<gsp, blk>>>((const float4*)q, (const float4*)k, (const float4*)v,
        (uint2*)q_hi, (uint2*)q_lo, (uint2*)k_hi, (uint2*)k_lo,
        (uint2*)v_hi, (uint2*)v_lo, n4_in);

    // launch 1: merged weight prep (Wq/Wk/Wv transpose + Wo permute)
    dim3 gtw(D_ / 32, D_ / 32, 4 * H_);
    prep_weights<<<gtw, blk>>>(Wq, Wk, Wv, Wo, A4_hi, A4_lo, B4_hi, B4_lo);

    // launch 2: C4[z] = A4[z] @ B4[z]^T  (z=16: MT=C4[0:8], P=C4[8:16]; 256 tiles)
    mma_gemm<1><<<nsm, blk, SMEM_T>>>(A4_hi, A4_lo, B4_hi, B4_lo,
        nullptr, C4_hi, C4_lo,
        256, 4, 4, D_, D_, D_, D_, sDD, sDD, 1, 2 * H_, 1, 2 * H_, 1, 0, 0,
        1, sDD, 1, 0, 1.0f);

    // launch 3: t[b,h] = q[b] @ MT[h]^T   (1024 tiles)
    mma_gemm<1><<<nsm, blk, SMEM_T>>>(q_hi, q_lo, C4_hi, C4_lo,
        nullptr, t_hi, t_lo,
        1024, 4, 16, D_, D_, D_, D_, sLD, sDD, H_, B_, 1, H_, 1, 0, 0,
        1, sLD, 1, 0, 1.0f);

    // launch 4: scores[b,h] = t[b,h] @ k[b]^T / sqrt(D)   (4096 tiles)
    mma_gemm<0><<<nsm, blk, SMEM_T>>>(t_hi, t_lo, k_hi, k_lo,
        attn, nullptr, nullptr,
        4096, 16, 16, D_, D_, D_, L_, sLD, sLD, 1, B_ * H_, H_, B_, 1, 0, 0,
        1, sLL, 1, 0, inv_sqrt_d);

    // launch 5: ZT[b, e, h*L+m] = P[h] @ v[b]^T  (1024 tiles)
    mma_gemm<1><<<nsm, blk, SMEM_T>>>(C4_hi + HDD, C4_lo + HDD, v_hi, v_lo,
        nullptr, ZT_hi, ZT_lo,
        1024, 16, 4, D_, D_, D_, H_ * L_, sDD, sLD, 1, H_, H_, B_, 1, 0, 0,
        H_, (long)D_ * H_ * L_, H_, (long)L_, 1.0f);

    // launch 6: softmax in place + bf16 hi/lo in permuted [b,l,h,m] layout
    softmax_split<<<B_ * H_ * L_, blk>>>(attn, (uint2*)at_hi, (uint2*)at_lo);

    // launch 7: out partials, split-K=8 over H*L (1024 tiles)
    mma_gemm<0><<<nsm, blk, SMEM_T>>>(at_hi, at_lo, ZT_hi, ZT_lo,
        part, nullptr, nullptr,
        1024, 4, 16, (H_ * L_) / KS_, H_ * L_, H_ * L_, D_,
        (long)L_ * H_ * L_, (long)D_ * H_ * L_, KS_, B_, KS_, B_,
        KS_, (H_ * L_) / KS_, (H_ * L_) / KS_,
        1, sLD, 1, 0, 1.0f);

    // launch 8: reduce partials -> out
    reduce_part<<<(B_ * L_ * D_ / 4) / 256, blk>>>((const float4*)part, (float4*)out);
}

// round 12
// speedup vs baseline: 1.3809x; 1.1310x over previous
#include <cuda_runtime.h>
#include <cuda_bf16.h>
#include <cuda_fp16.h>
#include <stdint.h>
#include <math.h>

#define B_  2
#define L_  2048
#define D_  512
#define H_  8
#define KS_ 8

// ======================= scratch (device globals) ==========================
__device__ __nv_bfloat16 g_q_hi [(size_t)B_*L_*D_];
__device__ __nv_bfloat16 g_q_lo [(size_t)B_*L_*D_];
__device__ __nv_bfloat16 g_k_hi [(size_t)B_*L_*D_];
__device__ __nv_bfloat16 g_k_lo [(size_t)B_*L_*D_];
__device__ __nv_bfloat16 g_v_hi [(size_t)B_*L_*D_];
__device__ __nv_bfloat16 g_v_lo [(size_t)B_*L_*D_];
// concatenated: A4 = [WkT | Wo'], B4 = [WqT | WvT], C4 = [MT | P]
__device__ __nv_bfloat16 g_A4_hi[(size_t)2*H_*D_*D_];
__device__ __nv_bfloat16 g_A4_lo[(size_t)2*H_*D_*D_];
__device__ __nv_bfloat16 g_B4_hi[(size_t)2*H_*D_*D_];
__device__ __nv_bfloat16 g_B4_lo[(size_t)2*H_*D_*D_];
__device__ __nv_bfloat16 g_C4_hi[(size_t)2*H_*D_*D_];
__device__ __nv_bfloat16 g_C4_lo[(size_t)2*H_*D_*D_];
__device__ __nv_bfloat16 g_t_hi [(size_t)B_*H_*L_*D_];
__device__ __nv_bfloat16 g_t_lo [(size_t)B_*H_*L_*D_];
__device__ __half        g_ZT_hi[(size_t)B_*D_*H_*L_];
__device__ __half        g_ZT_lo[(size_t)B_*D_*H_*L_];
__device__ __half        g_at_h [(size_t)B_*L_*H_*L_];   // fp16 single-limb attn
__device__ float         g_part [(size_t)B_*KS_*L_*D_];

// ======================= small helpers ======================================
__device__ __forceinline__ uint32_t smem_u32(const void* p) {
    uint32_t a;
    asm("{ .reg .u64 t; cvta.to.shared.u64 t, %1; cvt.u32.u64 %0, t; }"
        : "=r"(a) : "l"(p));
    return a;
}
__device__ __forceinline__ uint32_t swz128(uint32_t o) { return o ^ ((o >> 3) & 0x70); }

__device__ __forceinline__ void cp16(uint32_t s, const void* g) {
    asm volatile("cp.async.cg.shared.global [%0], [%1], 16;" :: "r"(s), "l"(g));
}
#define CP_COMMIT() asm volatile("cp.async.commit_group;" ::: "memory")

__device__ __forceinline__ void ldm4(uint32_t* r, uint32_t a) {
    asm volatile("ldmatrix.sync.aligned.m8n8.x4.shared.b16 {%0,%1,%2,%3}, [%4];"
                 : "=r"(r[0]), "=r"(r[1]), "=r"(r[2]), "=r"(r[3]) : "r"(a));
}
__device__ __forceinline__ void mma_bf16(float* c, const uint32_t* a, const uint32_t* b) {
    asm volatile("mma.sync.aligned.m16n8k16.row.col.f32.bf16.bf16.f32 "
                 "{%0,%1,%2,%3}, {%4,%5,%6,%7}, {%8,%9}, {%0,%1,%2,%3};"
                 : "+f"(c[0]), "+f"(c[1]), "+f"(c[2]), "+f"(c[3])
                 : "r"(a[0]), "r"(a[1]), "r"(a[2]), "r"(a[3]), "r"(b[0]), "r"(b[1]));
}
__device__ __forceinline__ void mma_f16(float* c, const uint32_t* a, const uint32_t* b) {
    asm volatile("mma.sync.aligned.m16n8k16.row.col.f32.f16.f16.f32 "
                 "{%0,%1,%2,%3}, {%4,%5,%6,%7}, {%8,%9}, {%0,%1,%2,%3};"
                 : "+f"(c[0]), "+f"(c[1]), "+f"(c[2]), "+f"(c[3])
                 : "r"(a[0]), "r"(a[1]), "r"(a[2]), "r"(a[3]), "r"(b[0]), "r"(b[1]));
}
__device__ __forceinline__ void split2(float x, __nv_bfloat16& h, __nv_bfloat16& l) {
    h = __float2bfloat16(x);
    l = __float2bfloat16(x - __bfloat162float(h));
}
__device__ __forceinline__ void split_pack(float2 v, uint32_t& hi, uint32_t& lo) {
    __nv_bfloat16 h0, l0, h1, l1;
    split2(v.x, h0, l0);
    split2(v.y, h1, l1);
    hi = ((uint32_t)__bfloat16_as_ushort(h1) << 16) | __bfloat16_as_ushort(h0);
    lo = ((uint32_t)__bfloat16_as_ushort(l1) << 16) | __bfloat16_as_ushort(l0);
}
__device__ __forceinline__ void split_pack_h(float2 v, uint32_t& hi, uint32_t& lo) {
    __half h0 = __float2half(v.x);
    __half l0 = __float2half(v.x - __half2float(h0));
    __half h1 = __float2half(v.y);
    __half l1 = __float2half(v.y - __half2float(h1));
    hi = ((uint32_t)__half_as_ushort(h1) << 16) | __half_as_ushort(h0);
    lo = ((uint32_t)__half_as_ushort(l1) << 16) | __half_as_ushort(l0);
}

// ============ persistent multi-limb HMMA GEMM (KC=64, 3-stage) ==============
// OUT: 0 fp32, 1 bf16 hi/lo pair, 2 f16 hi/lo pair
// AL:  2 = A two bf16 limbs (3 MMAs bf16), 1 = A one f16 limb (2 MMAs f16)
#define KC       64
#define TILE_B   (128 * 128)

struct TileP {
    const __nv_bfloat16 *ah, *al, *bh, *bl;
    long coff;
};

template <int OUT, int AL>
__global__ __launch_bounds__(256, 1)
void mma_gemm(const __nv_bfloat16* __restrict__ Ahi, const __nv_bfloat16* __restrict__ Alo,
              const __nv_bfloat16* __restrict__ Bhi, const __nv_bfloat16* __restrict__ Blo,
              float* __restrict__ C, __nv_bfloat16* __restrict__ Chi,
              __nv_bfloat16* __restrict__ Clo,
              int ntiles, int gx, int gy,
              int K, int lda, int ldb, int ldc,
              long sA, long sB, int adiv, int amod, int bdiv, int bmod,
              int azmod, long sA2, long sB2,
              int czdiv, long sC1, int czmod, long sC2, float alpha)
{
    constexpr int ATB = AL * TILE_B;          // A region bytes per stage
    constexpr int STB = (AL + 2) * TILE_B;    // stage bytes

    extern __shared__ char smem[];
    const uint32_t sb = smem_u32(smem);
    const int tid  = threadIdx.x;
    const int lane = tid & 31, wid = tid >> 5;
    const int moff = (wid & 1) * 64;
    const int noff = (wid >> 1) * 32;

    int t0 = blockIdx.x;
    if (t0 >= ntiles) return;

    auto tileinfo = [&](int t) -> TileP {
        const int gxy = gx * gy;
        const int z = t / gxy;
        const int r = t - z * gxy;
        const int ty = r / gx;
        const int tx = r - ty * gx;
        const long aoff = (long)((z / adiv) % amod) * sA + (long)(z % azmod) * sA2
                          + (long)ty * 128 * lda;
        const long boff = (long)((z / bdiv) % bmod) * sB + (long)(z % azmod) * sB2
                          + (long)tx * 128 * ldb;
        TileP p;
        p.ah = Ahi + aoff;  p.al = Alo + aoff;
        p.bh = Bhi + boff;  p.bl = Blo + boff;
        p.coff = (long)(z / czdiv) * sC1 + (long)(z % czmod) * sC2
                 + (long)ty * 128 * ldc + (long)tx * 128;
        return p;
    };

#define LOADT(T, cidx, stg) do {                                                 \
        const uint32_t st = sb + (stg) * STB;                                    \
        const int k0 = (cidx) * KC;                                              \
        _Pragma("unroll")                                                        \
        for (int it = 0; it < 4; it++) {                                         \
            const int idx = tid + it * 256;                                      \
            const int row = idx >> 3, ch = idx & 7;                              \
            const uint32_t so = swz128(row * 128 + ch * 16);                     \
            const long goA = (long)row * lda + k0 + ch * 8;                      \
            const long goB = (long)row * ldb + k0 + ch * 8;                      \
            cp16(st + so, (T).ah + goA);                                         \
            if (AL == 2) cp16(st + TILE_B + so, (T).al + goA);                   \
            cp16(st + ATB + so,          (T).bh + goB);                          \
            cp16(st + ATB + TILE_B + so, (T).bl + goB);                          \
        }                                                                        \
    } while (0)

    const int NC = K / KC;
    const int stride = gridDim.x;

    TileP cur = tileinfo(t0);
    LOADT(cur, 0, 0); CP_COMMIT();
    LOADT(cur, 1, 1); CP_COMMIT();
    int lstage = 2;
    int cstage = 0;

    const int arow = (lane & 7) + ((lane >> 3) & 1) * 8;
    const int ach  = (lane >> 4);
    const int brow = (lane & 7) + ((lane >> 4) & 1) * 8;
    const int bch  = ((lane >> 3) & 1);
    const int gq = lane >> 2, tg = lane & 3;

    for (int t = t0; t < ntiles; t += stride) {
        const int tn = t + stride;
        const bool has_next = tn < ntiles;
        TileP nxt = has_next ? tileinfo(tn) : cur;

        float acc[4][4][4];
#pragma unroll
        for (int a = 0; a < 4; a++)
#pragma unroll
            for (int b = 0; b < 4; b++)
#pragma unroll
                for (int c = 0; c < 4; c++) acc[a][b][c] = 0.f;

        for (int c = 0; c < NC; c++) {
            asm volatile("cp.async.wait_group 1;" ::: "memory");
            __syncthreads();
            const int cc = c + 2;
            if (cc < NC) {
                LOADT(cur, cc, lstage);
            } else if (has_next && cc - NC < 2) {
                LOADT(nxt, cc - NC, lstage);
            }
            CP_COMMIT();
            lstage = (lstage == 2) ? 0 : lstage + 1;

            const uint32_t st = sb + cstage * STB;
            cstage = (cstage == 2) ? 0 : cstage + 1;
#pragma unroll
            for (int kk = 0; kk < 4; kk++) {
                uint32_t ah[4][4], al[4][4], bh[4][2], bl[4][2];
#pragma unroll
                for (int mf = 0; mf < 4; mf++) {
                    uint32_t ad = st + swz128((moff + mf * 16 + arow) * 128 + (kk * 2 + ach) * 16);
                    ldm4(ah[mf], ad);
                    if (AL == 2) ldm4(al[mf], ad + TILE_B);
                }
#pragma unroll
                for (int p = 0; p < 2; p++) {
                    uint32_t bd = st + ATB +
                                  swz128((noff + p * 16 + brow) * 128 + (kk * 2 + bch) * 16);
                    uint32_t r[4];
                    ldm4(r, bd);
                    bh[2 * p][0] = r[0]; bh[2 * p][1] = r[1];
                    bh[2 * p + 1][0] = r[2]; bh[2 * p + 1][1] = r[3];
                    ldm4(r, bd + TILE_B);
                    bl[2 * p][0] = r[0]; bl[2 * p][1] = r[1];
                    bl[2 * p + 1][0] = r[2]; bl[2 * p + 1][1] = r[3];
                }
#pragma unroll
                for (int mf = 0; mf < 4; mf++)
#pragma unroll
                    for (int nf = 0; nf < 4; nf++) {
                        if (AL == 2) {
                            mma_bf16(acc[mf][nf], ah[mf], bh[nf]);
                            mma_bf16(acc[mf][nf], ah[mf], bl[nf]);
                            mma_bf16(acc[mf][nf], al[mf], bh[nf]);
                        } else {
                            mma_f16(acc[mf][nf], ah[mf], bh[nf]);
                            mma_f16(acc[mf][nf], ah[mf], bl[nf]);
                        }
                    }
            }
        }

        // ---- epilogue ----
#pragma unroll
        for (int mf = 0; mf < 4; mf++)
#pragma unroll
            for (int nf = 0; nf < 4; nf++) {
                const long row = moff + mf * 16 + gq;
                const long col = noff + nf * 8 + tg * 2;
                float v0 = alpha * acc[mf][nf][0];
                float v1 = alpha * acc[mf][nf][1];
                float v2 = alpha * acc[mf][nf][2];
                float v3 = alpha * acc[mf][nf][3];
                if (OUT == 0) {
                    float2 p0 = {v0, v1}, p1 = {v2, v3};
                    *reinterpret_cast<float2*>(C + cur.coff + row * ldc + col)       = p0;
                    *reinterpret_cast<float2*>(C + cur.coff + (row + 8) * ldc + col) = p1;
                } else {
                    uint32_t hp0, lp0, hp1, lp1;
                    if (OUT == 1) {
                        split_pack({v0, v1}, hp0, lp0);
                        split_pack({v2, v3}, hp1, lp1);
                    } else {
                        split_pack_h({v0, v1}, hp0, lp0);
                        split_pack_h({v2, v3}, hp1, lp1);
                    }
                    *reinterpret_cast<uint32_t*>(Chi + cur.coff + row * ldc + col)       = hp0;
                    *reinterpret_cast<uint32_t*>(Clo + cur.coff + row * ldc + col)       = lp0;
                    *reinterpret_cast<uint32_t*>(Chi + cur.coff + (row + 8) * ldc + col) = hp1;
                    *reinterpret_cast<uint32_t*>(Clo + cur.coff + (row + 8) * ldc + col) = lp1;
                }
            }
        cur = nxt;
    }
#undef LOADT
}

#define SMEM_T2 (3 * 4 * TILE_B)   // AL=2: 192 KB
#define SMEM_T1 (3 * 3 * TILE_B)   // AL=1: 144 KB

// ======================= helper kernels =====================================
__global__ __launch_bounds__(256)
void split_qkv(const float4* __restrict__ q, const float4* __restrict__ k,
               const float4* __restrict__ v,
               uint2* __restrict__ qh, uint2* __restrict__ ql,
               uint2* __restrict__ kh, uint2* __restrict__ kl,
               uint2* __restrict__ vh, uint2* __restrict__ vl, int n4)
{
    int i = blockIdx.x * 256 + threadIdx.x;
    if (i >= n4) return;
    const int sel = blockIdx.y;
    const float4* s = (sel == 0) ? q : (sel == 1) ? k : v;
    uint2* hi = (sel == 0) ? qh : (sel == 1) ? kh : vh;
    uint2* lo = (sel == 0) ? ql : (sel == 1) ? kl : vl;
    float4 x = s[i];
    __nv_bfloat16 h[4], l[4];
    split2(x.x, h[0], l[0]);
    split2(x.y, h[1], l[1]);
    split2(x.z, h[2], l[2]);
    split2(x.w, h[3], l[3]);
    hi[i] = *reinterpret_cast<uint2*>(h);
    lo[i] = *reinterpret_cast<uint2*>(l);
}

// merged weight prep: zz = w*8 + h; w<3 transpose-split, w==3 Wo permute-split
__global__ __launch_bounds__(256)
void prep_weights(const float* __restrict__ Wq, const float* __restrict__ Wk,
                  const float* __restrict__ Wv, const float* __restrict__ Wo,
                  __nv_bfloat16* __restrict__ A4hi, __nv_bfloat16* __restrict__ A4lo,
                  __nv_bfloat16* __restrict__ B4hi, __nv_bfloat16* __restrict__ B4lo)
{
    __shared__ float t[32][33];
    const int zz = blockIdx.z;
    const int w = zz >> 3, z = zz & 7;
    const long HDD = (long)H_ * D_ * D_;
    const int tx = threadIdx.x & 31, ty = threadIdx.x >> 5;

    if (w == 3) {
        const int e0 = blockIdx.y * 32, f0 = blockIdx.x * 32;
        const long base = HDD + (long)z * D_ * D_;
#pragma unroll
        for (int r = 0; r < 32; r += 8) {
            const int e = e0 + ty + r, f = f0 + tx;
            float x = Wo[(long)e * (H_ * D_) + (f >> 6) * 512 + z * 64 + (f & 63)];
            __nv_bfloat16 h, l;
            split2(x, h, l);
            long o = base + (long)e * D_ + f;
            A4hi[o] = h; A4lo[o] = l;
        }
        return;
    }

    const float* src = (w == 0) ? Wq : (w == 1) ? Wk : Wv;
    __nv_bfloat16* hi = (w == 0) ? B4hi : (w == 1) ? A4hi : (B4hi + HDD);
    __nv_bfloat16* lo = (w == 0) ? B4lo : (w == 1) ? A4lo : (B4lo + HDD);

    const int e0 = blockIdx.y * 32, d0 = blockIdx.x * 32;
    const float* s = src + (long)z * D_ * D_;
#pragma unroll
    for (int r = 0; r < 32; r += 8)
        t[ty + r][tx] = s[(long)(e0 + ty + r) * D_ + d0 + tx];
    __syncthreads();
    const long base = (long)z * D_ * D_;
#pragma unroll
    for (int r = 0; r < 32; r += 8) {
        float x = t[tx][ty + r];
        __nv_bfloat16 h, l;
        split2(x, h, l);
        long o = base + (long)(d0 + ty + r) * D_ + e0 + tx;
        hi[o] = h; lo[o] = l;
    }
}

// softmax: in place fp32 [b,h,l,m] + fp16 single-limb copy in [b,l,h,m]
__global__ __launch_bounds__(256)
void softmax_split(float* __restrict__ data, uint2* __restrict__ hi)
{
    const int r = blockIdx.x;
    const int b = r >> 14;
    const int h = (r >> 11) & (H_ - 1);
    const int l = r & (L_ - 1);
    float4* p = reinterpret_cast<float4*>(data + (long)r * L_);
    const long ob4 = ((((long)b * L_ + l) * H_ + h) * L_) >> 2;   // in 4-elem units
    const int tid = threadIdx.x;

    float4 vals[2];
    float vmax = -1e30f;
#pragma unroll
    for (int i = 0; i < 2; i++) {
        vals[i] = p[tid + i * 256];
        vmax = fmaxf(vmax, fmaxf(fmaxf(vals[i].x, vals[i].y), fmaxf(vals[i].z, vals[i].w)));
    }
#pragma unroll
    for (int o = 16; o > 0; o >>= 1) vmax = fmaxf(vmax, __shfl_xor_sync(0xFFFFFFFFu, vmax, o));

    __shared__ float smax[8], ssum[8];
    if ((tid & 31) == 0) smax[tid >> 5] = vmax;
    __syncthreads();
    float m = smax[0];
#pragma unroll
    for (int i = 1; i < 8; i++) m = fmaxf(m, smax[i]);

    float sum = 0.f;
#pragma unroll
    for (int i = 0; i < 2; i++) {
        vals[i].x = __expf(vals[i].x - m);
        vals[i].y = __expf(vals[i].y - m);
        vals[i].z = __expf(vals[i].z - m);
        vals[i].w = __expf(vals[i].w - m);
        sum += (vals[i].x + vals[i].y) + (vals[i].z + vals[i].w);
    }
#pragma unroll
    for (int o = 16; o > 0; o >>= 1) sum += __shfl_xor_sync(0xFFFFFFFFu, sum, o);
    if ((tid & 31) == 0) ssum[tid >> 5] = sum;
    __syncthreads();
    float tot = 0.f;
#pragma unroll
    for (int i = 0; i < 8; i++) tot += ssum[i];
    const float inv = 1.f / tot;
#pragma unroll
    for (int i = 0; i < 2; i++) {
        float4 y;
        y.x = vals[i].x * inv; y.y = vals[i].y * inv;
        y.z = vals[i].z * inv; y.w = vals[i].w * inv;
        p[tid + i * 256] = y;
        __half h0 = __float2half(y.x), h1 = __float2half(y.y);
        __half h2 = __float2half(y.z), h3 = __float2half(y.w);
        uint2 hp;
        hp.x = ((uint32_t)__half_as_ushort(h1) << 16) | __half_as_ushort(h0);
        hp.y = ((uint32_t)__half_as_ushort(h3) << 16) | __half_as_ushort(h2);
        hi[ob4 + tid + i * 256] = hp;
    }
}

// reduce partials: out[b][j] = sum_ks part[b*KS+ks][j]
__global__ __launch_bounds__(256)
void reduce_part(const float4* __restrict__ part, float4* __restrict__ out)
{
    const int LD4 = L_ * D_ / 4;
    long idx = (long)blockIdx.x * 256 + threadIdx.x;
    int b = (int)(idx / LD4);
    long j = idx - (long)b * LD4;
    const float4* p = part + (long)b * KS_ * LD4 + j;
    float4 s = p[0];
#pragma unroll
    for (int ks = 1; ks < KS_; ks++) {
        float4 t = p[(long)ks * LD4];
        s.x += t.x; s.y += t.y; s.z += t.z; s.w += t.w;
    }
    out[idx] = s;
}

// ======================= launch =============================================
extern "C" void kernel_launch(void* const* d_in, const int* in_sizes, int n_in,
                              void* d_out, int out_size)
{
    const float* q  = (const float*)d_in[0];
    const float* k  = (const float*)d_in[1];
    const float* v  = (const float*)d_in[2];
    const float* Wq = (const float*)d_in[3];
    const float* Wk = (const float*)d_in[4];
    const float* Wv = (const float*)d_in[5];
    const float* Wo = (const float*)d_in[6];

    float* out  = (float*)d_out;
    float* attn = out + (long)B_ * L_ * D_;

    static int nsm = 0;
    if (!nsm) {
        cudaDeviceGetAttribute(&nsm, cudaDevAttrMultiProcessorCount, 0);
        cudaFuncSetAttribute(mma_gemm<0, 2>, cudaFuncAttributeMaxDynamicSharedMemorySize, SMEM_T2);
        cudaFuncSetAttribute(mma_gemm<1, 2>, cudaFuncAttributeMaxDynamicSharedMemorySize, SMEM_T2);
        cudaFuncSetAttribute(mma_gemm<2, 2>, cudaFuncAttributeMaxDynamicSharedMemorySize, SMEM_T2);
        cudaFuncSetAttribute(mma_gemm<0, 1>, cudaFuncAttributeMaxDynamicSharedMemorySize, SMEM_T1);
        if (nsm <= 0) nsm = 148;
    }

#define SYM(p, s) cudaGetSymbolAddress((void**)&p, s)
    __nv_bfloat16 *q_hi, *q_lo, *k_hi, *k_lo, *v_hi, *v_lo;
    __nv_bfloat16 *A4_hi, *A4_lo, *B4_hi, *B4_lo, *C4_hi, *C4_lo;
    __nv_bfloat16 *t_hi, *t_lo;
    __half *ZT_hi, *ZT_lo, *at_h;
    float *part;
    SYM(q_hi, g_q_hi);  SYM(q_lo, g_q_lo);
    SYM(k_hi, g_k_hi);  SYM(k_lo, g_k_lo);
    SYM(v_hi, g_v_hi);  SYM(v_lo, g_v_lo);
    SYM(A4_hi, g_A4_hi); SYM(A4_lo, g_A4_lo);
    SYM(B4_hi, g_B4_hi); SYM(B4_lo, g_B4_lo);
    SYM(C4_hi, g_C4_hi); SYM(C4_lo, g_C4_lo);
    SYM(t_hi, g_t_hi);   SYM(t_lo, g_t_lo);
    SYM(ZT_hi, g_ZT_hi); SYM(ZT_lo, g_ZT_lo);
    SYM(at_h, g_at_h);
    SYM(part, g_part);
#undef SYM

    const long sLD = (long)L_ * D_;
    const long sLL = (long)L_ * L_;
    const long sDD = (long)D_ * D_;
    const long HDD = (long)H_ * D_ * D_;
    const float inv_sqrt_d = 1.0f / sqrtf((float)D_);

    dim3 blk(256);
    const int n4_in = (B_ * L_ * D_) / 4;

    // launch 0: merged q/k/v splits
    dim3 gsp((n4_in + 255) / 256, 3);
    split_qkv<<<gsp, blk>>>((const float4*)q, (const float4*)k, (const float4*)v,
        (uint2*)q_hi, (uint2*)q_lo, (uint2*)k_hi, (uint2*)k_lo,
        (uint2*)v_hi, (uint2*)v_lo, n4_in);

    // launch 1: merged weight prep
    dim3 gtw(D_ / 32, D_ / 32, 4 * H_);
    prep_weights<<<gtw, blk>>>(Wq, Wk, Wv, Wo, A4_hi, A4_lo, B4_hi, B4_lo);

    // launch 2: C4[z] = A4[z] @ B4[z]^T  (256 tiles)
    mma_gemm<1, 2><<<nsm, blk, SMEM_T2>>>(A4_hi, A4_lo, B4_hi, B4_lo,
        nullptr, C4_hi, C4_lo,
        256, 4, 4, D_, D_, D_, D_, sDD, sDD, 1, 2 * H_, 1, 2 * H_, 1, 0, 0,
        1, sDD, 1, 0, 1.0f);

    // launch 3: ZT[b, e, h*L+m] = P[h] @ v[b]^T -> fp16 pair (1024 tiles)
    mma_gemm<2, 2><<<nsm, blk, SMEM_T2>>>(C4_hi + HDD, C4_lo + HDD, v_hi, v_lo,
        nullptr, (__nv_bfloat16*)ZT_hi, (__nv_bfloat16*)ZT_lo,
        1024, 16, 4, D_, D_, D_, H_ * L_, sDD, sLD, 1, H_, H_, B_, 1, 0, 0,
        H_, (long)D_ * H_ * L_, H_, (long)L_, 1.0f);

    // launch 4: t[b,h] = q[b] @ MT[h]^T   (1024 tiles)
    mma_gemm<1, 2><<<nsm, blk, SMEM_T2>>>(q_hi, q_lo, C4_hi, C4_lo,
        nullptr, t_hi, t_lo,
        1024, 4, 16, D_, D_, D_, D_, sLD, sDD, H_, B_, 1, H_, 1, 0, 0,
        1, sLD, 1, 0, 1.0f);

    // launch 5 (ncu capture): scores[b,h] = t[b,h] @ k[b]^T / sqrt(D) (4096 tiles)
    mma_gemm<0, 2><<<nsm, blk, SMEM_T2>>>(t_hi, t_lo, k_hi, k_lo,
        attn, nullptr, nullptr,
        4096, 16, 16, D_, D_, D_, L_, sLD, sLD, 1, B_ * H_, H_, B_, 1, 0, 0,
        1, sLL, 1, 0, inv_sqrt_d);

    // launch 6: softmax in place + fp16 single-limb copy in [b,l,h,m] layout
    softmax_split<<<B_ * H_ * L_, blk>>>(attn, (uint2*)at_h);

    // launch 7: out partials, split-K=8 over H*L, A = fp16 attn (1024 tiles)
    mma_gemm<0, 1><<<nsm, blk, SMEM_T1>>>((const __nv_bfloat16*)at_h,
        (const __nv_bfloat16*)at_h,
        (const __nv_bfloat16*)ZT_hi, (const __nv_bfloat16*)ZT_lo,
        part, nullptr, nullptr,
        1024, 4, 16, (H_ * L_) / KS_, H_ * L_, H_ * L_, D_,
        (long)L_ * H_ * L_, (long)D_ * H_ * L_, KS_, B_, KS_, B_,
        KS_, (H_ * L_) / KS_, (H_ * L_) / KS_,
        1, sLD, 1, 0, 1.0f);

    // launch 8: reduce partials -> out
    reduce_part<<<(B_ * L_ * D_ / 4) / 256, blk>>>((const float4*)part, (float4*)out);
}